// round 5
// baseline (speedup 1.0000x reference)
#include <cuda_runtime.h>
#include <cuda_bf16.h>
#include <cstdint>

#define BB 8
#define SS 4096
#define DD 256
#define NROWS (BB*SS)
#define NEGV  (-1000000000.0f)
#define NSPLIT 4
#define KSPLIT (SS/NSPLIT)   // 1024
#define NCH1 (KSPLIT/32)     // 32
#define NCH2 (DD/32)         // 8
#define P1 272               // pitch bytes, 32-row tiles (128 bf16 + pad)
#define P2 80                // pitch bytes, 128-row A tiles (32 bf16 + pad)
#define BUFQ1 (32*P1)        // 8704
#define BUF1  (4*BUFQ1)      // 34816  (Ah,Al,Bh,Bl)
#define BUF2  (2*128*P2 + 2*32*P1)   // 37888 (Ah,Al,Bh,Bl)

// ---- scratch ----
__device__ float g_inv_b[NROWS];
__device__ float g_s1[BB*DD*DD];
__device__ float g_s1p4[NSPLIT][BB*DD*DD];
__device__ float g_colsum[BB*DD];
__device__ int   g_mask_kind;

// ============================ helpers ============================
__device__ __forceinline__ uint32_t smem_u32(const void* p) {
    uint32_t a;
    asm("{ .reg .u64 t; cvta.to.shared.u64 t, %1; cvt.u32.u64 %0, t; }"
        : "=r"(a) : "l"(p));
    return a;
}
__device__ __forceinline__ void ldsm_x4(uint32_t* r, uint32_t a) {
    asm volatile("ldmatrix.sync.aligned.m8n8.x4.shared.b16 {%0,%1,%2,%3}, [%4];"
        : "=r"(r[0]), "=r"(r[1]), "=r"(r[2]), "=r"(r[3]) : "r"(a));
}
__device__ __forceinline__ void ldsm_x4t(uint32_t* r, uint32_t a) {
    asm volatile("ldmatrix.sync.aligned.m8n8.x4.trans.shared.b16 {%0,%1,%2,%3}, [%4];"
        : "=r"(r[0]), "=r"(r[1]), "=r"(r[2]), "=r"(r[3]) : "r"(a));
}
__device__ __forceinline__ void mma_bf16(float* c, const uint32_t* a, const uint32_t* b) {
    asm volatile(
        "mma.sync.aligned.m16n8k16.row.col.f32.bf16.bf16.f32 "
        "{%0,%1,%2,%3}, {%4,%5,%6,%7}, {%8,%9}, {%0,%1,%2,%3};"
        : "+f"(c[0]), "+f"(c[1]), "+f"(c[2]), "+f"(c[3])
        : "r"(a[0]), "r"(a[1]), "r"(a[2]), "r"(a[3]), "r"(b[0]), "r"(b[1]));
}
__device__ __forceinline__ void hilo(float x0, float x1, uint32_t& h, uint32_t& l) {
    __nv_bfloat162 hh = __floats2bfloat162_rn(x0, x1);
    float h0 = __bfloat162float(hh.x);
    float h1 = __bfloat162float(hh.y);
    __nv_bfloat162 ll = __floats2bfloat162_rn(x0 - h0, x1 - h1);
    h = *reinterpret_cast<uint32_t*>(&hh);
    l = *reinterpret_cast<uint32_t*>(&ll);
}
__device__ __forceinline__ bool is_masked(const void* mask, int row) {
    int kind = g_mask_kind;
    if (kind == 1) return ((const unsigned char*)mask)[row] != 0;
    if (kind == 2) return ((const float*)mask)[row] != 0.0f;
    return ((const int*)mask)[row] != 0;
}

// ============================ Kernel 0: mask sniff + zero colsum ============================
__global__ void k_detect(const unsigned int* __restrict__ m) {
    __shared__ int s_u8, s_f;
    if (threadIdx.x == 0) { s_u8 = 0; s_f = 0; }
    __syncthreads();
    for (int i = threadIdx.x; i < 8192; i += 256) {
        unsigned v = m[i];
        if (v == 0x3F800000u)      s_f  = 1;
        else if (v > 1u)           s_u8 = 1;
    }
    for (int i = threadIdx.x; i < BB * DD; i += 256) g_colsum[i] = 0.f;
    __syncthreads();
    if (threadIdx.x == 0) g_mask_kind = s_u8 ? 1 : (s_f ? 2 : 0);
}

// ============================ Kernel 1: K row norms only ============================
__global__ void k_knorm(const float* __restrict__ k) {
    int row  = blockIdx.x * 8 + (threadIdx.x >> 5);
    int lane = threadIdx.x & 31;
    const float4* k4 = (const float4*)(k + (size_t)row * DD);
    float sb = 0.f;
#pragma unroll
    for (int j = 0; j < 2; j++) {
        float4 b = k4[lane + 32 * j];
        sb += b.x*b.x + b.y*b.y + b.z*b.z + b.w*b.w;
    }
#pragma unroll
    for (int o = 16; o; o >>= 1) sb += __shfl_xor_sync(0xFFFFFFFFu, sb, o);
    if (lane == 0) g_inv_b[row] = 1.0f / sb;
}

// ============================ Kernel 2: GEMM1 (pipelined bf16-split mma) ============================
__global__ void __launch_bounds__(256, 1)
k_g1(const float* __restrict__ K, const float* __restrict__ V) {
    extern __shared__ __align__(16) char sm[];
    const uint32_t sb = smem_u32(sm);
    const int tid = threadIdx.x, lane = tid & 31, wid = tid >> 5;
    const int b = blockIdx.z, split = blockIdx.y;
    const int m0 = (blockIdx.x >> 1) * 128, n0 = (blockIdx.x & 1) * 128;
    const float* Kb   = K + (size_t)b * SS * DD;
    const float* Vb   = V + (size_t)b * SS * DD;
    const float* invb = g_inv_b + b * SS;

    const int sl = tid >> 3, q0 = tid & 7;
    const int wm = (wid >> 2) * 64, wn = (wid & 3) * 32;
    const int rowT = (lane & 7) + ((lane >> 4) << 3);
    const int colT = ((lane >> 3) & 1) << 3;
    const int rowB = lane & 15;
    const int colB = (lane >> 4) << 3;

    float acc[4][4][4];
#pragma unroll
    for (int i = 0; i < 4; i++)
#pragma unroll
        for (int j = 0; j < 4; j++)
#pragma unroll
            for (int t = 0; t < 4; t++) acc[i][j][t] = 0.f;

    float4 rk[4], rv[4]; float ib;
    // ---- load chunk 0 ----
    {
        int s = split * KSPLIT + sl;
        const float* kr = Kb + (size_t)s * DD + m0;
        const float* vr = Vb + (size_t)s * DD + n0;
        ib = invb[s];
#pragma unroll
        for (int j = 0; j < 4; j++) {
            rk[j] = *(const float4*)(kr + 4 * (q0 + 8 * j));
            rv[j] = *(const float4*)(vr + 4 * (q0 + 8 * j));
        }
    }
    // ---- convert+store chunk 0 -> buf0 ----
    {
        char* Ah = sm; char* Al = sm + BUFQ1; char* Bh = sm + 2*BUFQ1; char* Bl = sm + 3*BUFQ1;
#pragma unroll
        for (int j = 0; j < 4; j++) {
            int off = sl * P1 + 8 * (q0 + 8 * j);
            uint32_t h01, l01, h23, l23;
            hilo(rk[j].x * ib, rk[j].y * ib, h01, l01);
            hilo(rk[j].z * ib, rk[j].w * ib, h23, l23);
            *(uint2*)(Ah + off) = make_uint2(h01, h23);
            *(uint2*)(Al + off) = make_uint2(l01, l23);
            hilo(rv[j].x, rv[j].y, h01, l01);
            hilo(rv[j].z, rv[j].w, h23, l23);
            *(uint2*)(Bh + off) = make_uint2(h01, h23);
            *(uint2*)(Bl + off) = make_uint2(l01, l23);
        }
    }
    __syncthreads();

    for (int c = 0; c < NCH1; c++) {
        // prefetch chunk c+1 (latency hidden by mma below)
        if (c + 1 < NCH1) {
            int s = split * KSPLIT + (c + 1) * 32 + sl;
            const float* kr = Kb + (size_t)s * DD + m0;
            const float* vr = Vb + (size_t)s * DD + n0;
            ib = invb[s];
#pragma unroll
            for (int j = 0; j < 4; j++) {
                rk[j] = *(const float4*)(kr + 4 * (q0 + 8 * j));
                rv[j] = *(const float4*)(vr + 4 * (q0 + 8 * j));
            }
        }
        // mma on buf[c&1]
        const uint32_t ub = sb + (uint32_t)(c & 1) * BUF1;
        const uint32_t uAh = ub, uAl = ub + BUFQ1, uBh = ub + 2*BUFQ1, uBl = ub + 3*BUFQ1;
#pragma unroll
        for (int ks = 0; ks < 32; ks += 16) {
            uint32_t ah[4][4], al[4][4], bh[4][2], bl[4][2];
#pragma unroll
            for (int mf = 0; mf < 4; mf++) {
                uint32_t a = (uint32_t)((ks + rowT) * P1 + 2 * (wm + mf * 16 + colT));
                ldsm_x4t(ah[mf], uAh + a);
                ldsm_x4t(al[mf], uAl + a);
            }
#pragma unroll
            for (int nb = 0; nb < 2; nb++) {
                uint32_t a = (uint32_t)((ks + rowB) * P1 + 2 * (wn + nb * 16 + colB));
                ldsm_x4t(&bh[nb * 2][0], uBh + a);
                ldsm_x4t(&bl[nb * 2][0], uBl + a);
            }
#pragma unroll
            for (int mi = 0; mi < 4; mi++)
#pragma unroll
                for (int ni = 0; ni < 4; ni++) {
                    mma_bf16(acc[mi][ni], ah[mi], bh[ni]);
                    mma_bf16(acc[mi][ni], ah[mi], bl[ni]);
                    mma_bf16(acc[mi][ni], al[mi], bh[ni]);
                }
        }
        // convert+store chunk c+1 -> buf[(c+1)&1]
        if (c + 1 < NCH1) {
            char* bp = sm + ((c + 1) & 1) * BUF1;
            char* Ah = bp; char* Al = bp + BUFQ1; char* Bh = bp + 2*BUFQ1; char* Bl = bp + 3*BUFQ1;
#pragma unroll
            for (int j = 0; j < 4; j++) {
                int off = sl * P1 + 8 * (q0 + 8 * j);
                uint32_t h01, l01, h23, l23;
                hilo(rk[j].x * ib, rk[j].y * ib, h01, l01);
                hilo(rk[j].z * ib, rk[j].w * ib, h23, l23);
                *(uint2*)(Ah + off) = make_uint2(h01, h23);
                *(uint2*)(Al + off) = make_uint2(l01, l23);
                hilo(rv[j].x, rv[j].y, h01, l01);
                hilo(rv[j].z, rv[j].w, h23, l23);
                *(uint2*)(Bh + off) = make_uint2(h01, h23);
                *(uint2*)(Bl + off) = make_uint2(l01, l23);
            }
        }
        __syncthreads();
    }

    float* out = g_s1p4[split] + (size_t)b * DD * DD;
    const int r0 = lane >> 2, cp = (lane & 3) * 2;
#pragma unroll
    for (int mi = 0; mi < 4; mi++)
#pragma unroll
        for (int ni = 0; ni < 4; ni++) {
            int m = m0 + wm + mi * 16 + r0;
            int n = n0 + wn + ni * 8 + cp;
            *(float2*)(out + (size_t)m * DD + n)       = make_float2(acc[mi][ni][0], acc[mi][ni][1]);
            *(float2*)(out + (size_t)(m + 8) * DD + n) = make_float2(acc[mi][ni][2], acc[mi][ni][3]);
        }
}

// ============================ Kernel 3: reduce partials (float4) ============================
__global__ void k_reduce() {
    int i = blockIdx.x * 256 + threadIdx.x;     // over BB*DD*DD/4
    float4 a = ((const float4*)g_s1p4[0])[i];
    float4 b = ((const float4*)g_s1p4[1])[i];
    float4 c = ((const float4*)g_s1p4[2])[i];
    float4 d = ((const float4*)g_s1p4[3])[i];
    ((float4*)g_s1)[i] = make_float4(a.x+b.x+c.x+d.x, a.y+b.y+c.y+d.y,
                                     a.z+b.z+c.z+d.z, a.w+b.w+c.w+d.w);
}

// ============================ Kernel 4: column sums (parallel + atomic) ============================
__global__ void k_colsum() {   // grid (8 dchunks, 8 b), 256 threads
    int b = blockIdx.y, dc = blockIdx.x, e = threadIdx.x;
    const float* s1b = g_s1 + (size_t)b * DD * DD + dc * 32 * DD;
    float s = 0.f;
#pragma unroll
    for (int d = 0; d < 32; d++) s += s1b[d * DD + e];
    atomicAdd(&g_colsum[b * DD + e], s);
}

// ============================ Kernel 5: GEMM2 (pipelined, fused q-norm) ============================
__global__ void __launch_bounds__(256, 1)
k_g2(const float* __restrict__ Q, const void* __restrict__ mask,
     float* __restrict__ Out) {
    extern __shared__ __align__(16) char sm[];
    const uint32_t sb = smem_u32(sm);
    const int tid = threadIdx.x, lane = tid & 31, wid = tid >> 5;
    const int b = blockIdx.z, m0 = blockIdx.y * 128, n0 = blockIdx.x * 128;
    const float* Qb  = Q + (size_t)b * SS * DD;
    const float* s1b = g_s1 + (size_t)b * DD * DD;
    float* smul = (float*)(sm + 2 * BUF2);

    const int ar = tid >> 1, aq0 = tid & 1;     // A loader: 2 thr/row
    const int blr = tid >> 3, bq0 = tid & 7;    // B loader: 8 thr/row
    const int wm = (wid >> 2) * 64, wn = (wid & 3) * 32;
    const int rowA = lane & 15, colA = (lane >> 4) << 3;
    const int rowB = lane & 15, colB = (lane >> 4) << 3;

    float acc[4][4][4];
#pragma unroll
    for (int i = 0; i < 4; i++)
#pragma unroll
        for (int j = 0; j < 4; j++)
#pragma unroll
            for (int t = 0; t < 4; t++) acc[i][j][t] = 0.f;

    float qss = 0.f;
    float4 ra[4], rb[4];
    // ---- load chunk 0 ----
    {
        const float* qr = Qb + (size_t)(m0 + ar) * DD;
#pragma unroll
        for (int j = 0; j < 4; j++) {
            ra[j] = *(const float4*)(qr + 4 * (aq0 + 2 * j));
            qss += ra[j].x*ra[j].x + ra[j].y*ra[j].y + ra[j].z*ra[j].z + ra[j].w*ra[j].w;
            rb[j] = *(const float4*)(s1b + (size_t)blr * DD + n0 + 4 * (bq0 + 8 * j));
        }
    }
    // ---- convert+store chunk 0 -> buf0 ----
    {
        char* Ah = sm; char* Al = sm + 128*P2;
        char* Bh = sm + 2*128*P2; char* Bl = Bh + 32*P1;
#pragma unroll
        for (int j = 0; j < 4; j++) {
            int off = ar * P2 + 8 * (aq0 + 2 * j);
            uint32_t h01, l01, h23, l23;
            hilo(ra[j].x, ra[j].y, h01, l01);
            hilo(ra[j].z, ra[j].w, h23, l23);
            *(uint2*)(Ah + off) = make_uint2(h01, h23);
            *(uint2*)(Al + off) = make_uint2(l01, l23);
            int offb = blr * P1 + 8 * (bq0 + 8 * j);
            hilo(rb[j].x, rb[j].y, h01, l01);
            hilo(rb[j].z, rb[j].w, h23, l23);
            *(uint2*)(Bh + offb) = make_uint2(h01, h23);
            *(uint2*)(Bl + offb) = make_uint2(l01, l23);
        }
    }
    __syncthreads();

    for (int c = 0; c < NCH2; c++) {
        if (c + 1 < NCH2) {
            int k0 = (c + 1) * 32;
            const float* qr = Qb + (size_t)(m0 + ar) * DD + k0;
#pragma unroll
            for (int j = 0; j < 4; j++) {
                ra[j] = *(const float4*)(qr + 4 * (aq0 + 2 * j));
                qss += ra[j].x*ra[j].x + ra[j].y*ra[j].y + ra[j].z*ra[j].z + ra[j].w*ra[j].w;
                rb[j] = *(const float4*)(s1b + (size_t)(k0 + blr) * DD + n0 + 4 * (bq0 + 8 * j));
            }
        }
        const uint32_t ub = sb + (uint32_t)(c & 1) * BUF2;
        const uint32_t uAh = ub, uAl = ub + 128*P2;
        const uint32_t uBh = ub + 2*128*P2, uBl = uBh + 32*P1;
#pragma unroll
        for (int ks = 0; ks < 32; ks += 16) {
            uint32_t ah[4][4], al[4][4], bh[4][2], bl[4][2];
#pragma unroll
            for (int mf = 0; mf < 4; mf++) {
                uint32_t a = (uint32_t)((wm + mf * 16 + rowA) * P2 + 2 * (ks + colA));
                ldsm_x4(ah[mf], uAh + a);
                ldsm_x4(al[mf], uAl + a);
            }
#pragma unroll
            for (int nb = 0; nb < 2; nb++) {
                uint32_t a = (uint32_t)((ks + rowB) * P1 + 2 * (wn + nb * 16 + colB));
                ldsm_x4t(&bh[nb * 2][0], uBh + a);
                ldsm_x4t(&bl[nb * 2][0], uBl + a);
            }
#pragma unroll
            for (int mi = 0; mi < 4; mi++)
#pragma unroll
                for (int ni = 0; ni < 4; ni++) {
                    mma_bf16(acc[mi][ni], ah[mi], bh[ni]);
                    mma_bf16(acc[mi][ni], ah[mi], bl[ni]);
                    mma_bf16(acc[mi][ni], al[mi], bh[ni]);
                }
        }
        if (c + 1 < NCH2) {
            char* bp = sm + ((c + 1) & 1) * BUF2;
            char* Ah = bp; char* Al = bp + 128*P2;
            char* Bh = bp + 2*128*P2; char* Bl = Bh + 32*P1;
#pragma unroll
            for (int j = 0; j < 4; j++) {
                int off = ar * P2 + 8 * (aq0 + 2 * j);
                uint32_t h01, l01, h23, l23;
                hilo(ra[j].x, ra[j].y, h01, l01);
                hilo(ra[j].z, ra[j].w, h23, l23);
                *(uint2*)(Ah + off) = make_uint2(h01, h23);
                *(uint2*)(Al + off) = make_uint2(l01, l23);
                int offb = blr * P1 + 8 * (bq0 + 8 * j);
                hilo(rb[j].x, rb[j].y, h01, l01);
                hilo(rb[j].z, rb[j].w, h23, l23);
                *(uint2*)(Bh + offb) = make_uint2(h01, h23);
                *(uint2*)(Bl + offb) = make_uint2(l01, l23);
            }
        }
        __syncthreads();
    }

    // per-row scale (and mask flag via mul==0) into smem
    qss += __shfl_xor_sync(0xFFFFFFFFu, qss, 1);
    if (aq0 == 0) {
        int grow = b * SS + m0 + ar;
        smul[ar] = is_masked(mask, grow) ? 0.0f : 1.0f / qss;
    }
    __syncthreads();

    const float sc = 1.0f / 256.0f;
    const float* cs = g_colsum + b * DD;
    const int r0 = lane >> 2, cp = (lane & 3) * 2;
#pragma unroll
    for (int mi = 0; mi < 4; mi++) {
        int m1 = m0 + wm + mi * 16 + r0;
        int m2 = m1 + 8;
        float mu1 = smul[m1 - m0], mu2 = smul[m2 - m0];
        bool k1 = (mu1 == 0.0f), k2 = (mu2 == 0.0f);
        float* o1 = Out + ((size_t)b * SS + m1) * DD;
        float* o2 = Out + ((size_t)b * SS + m2) * DD;
        float s1f = mu1 * sc, s2f = mu2 * sc;
#pragma unroll
        for (int ni = 0; ni < 4; ni++) {
            int n = n0 + wn + ni * 8 + cp;
            float cs0 = cs[n] * (NEGV * sc), cs1 = cs[n + 1] * (NEGV * sc);
            float v0 = k1 ? cs0 : acc[mi][ni][0] * s1f;
            float v1 = k1 ? cs1 : acc[mi][ni][1] * s1f;
            float v2 = k2 ? cs0 : acc[mi][ni][2] * s2f;
            float v3 = k2 ? cs1 : acc[mi][ni][3] * s2f;
            *(float2*)(o1 + n) = make_float2(v0, v1);
            *(float2*)(o2 + n) = make_float2(v2, v3);
        }
    }
}

// ===========================================================================
extern "C" void kernel_launch(void* const* d_in, const int* in_sizes, int n_in,
                              void* d_out, int out_size) {
    const float* q    = (const float*)d_in[0];
    const float* k    = (const float*)d_in[1];
    const float* v    = (const float*)d_in[2];
    const void*  mask = d_in[3];
    float* out = (float*)d_out;

    const int SMEM_G1 = 2 * BUF1;         // 69632
    const int SMEM_G2 = 2 * BUF2 + 512;   // 76288
    cudaFuncSetAttribute(k_g1, cudaFuncAttributeMaxDynamicSharedMemorySize, SMEM_G1);
    cudaFuncSetAttribute(k_g2, cudaFuncAttributeMaxDynamicSharedMemorySize, SMEM_G2);

    k_detect<<<1, 256>>>((const unsigned int*)mask);
    k_knorm<<<NROWS / 8, 256>>>(k);
    k_g1<<<dim3(4, NSPLIT, BB), 256, SMEM_G1>>>(k, v);
    k_reduce<<<(BB * DD * DD / 4) / 256, 256>>>();
    k_colsum<<<dim3(8, 8), 256>>>();
    k_g2<<<dim3(2, SS / 128, BB), 256, SMEM_G2>>>(q, mask, out);
}

// round 6
// speedup vs baseline: 1.1758x; 1.1758x over previous
#include <cuda_runtime.h>
#include <cuda_fp16.h>
#include <cstdint>

#define BB 8
#define SS 4096
#define DD 256
#define NROWS (BB*SS)
#define NEGV  (-1000000000.0f)
#define NSPLIT 4
#define KSPLIT (SS/NSPLIT)   // 1024
#define NCH1 (KSPLIT/32)     // 32
#define NCH2 (DD/32)         // 8
#define P1 272               // pitch bytes, 32-row tiles (128 fp16 + pad)
#define P2 80                // pitch bytes, 128-row A tiles (32 fp16 + pad)
#define BUFQ1 (32*P1)        // 8704
#define BUF1  (3*BUFQ1)      // 26112  (Ah,Al,Bh)
#define A2SZ  (128*P2)       // 10240
#define BUF2  (2*A2SZ + 32*P1)   // 29184 (Ah,Al,Bh)

// ---- scratch ----
__device__ float g_inv_b[NROWS];
__device__ float g_s1[BB*DD*DD];
__device__ float g_s1p4[NSPLIT][BB*DD*DD];
__device__ int   g_mask_kind;

// ============================ helpers ============================
__device__ __forceinline__ uint32_t smem_u32(const void* p) {
    uint32_t a;
    asm("{ .reg .u64 t; cvta.to.shared.u64 t, %1; cvt.u32.u64 %0, t; }"
        : "=r"(a) : "l"(p));
    return a;
}
__device__ __forceinline__ void ldsm_x4(uint32_t* r, uint32_t a) {
    asm volatile("ldmatrix.sync.aligned.m8n8.x4.shared.b16 {%0,%1,%2,%3}, [%4];"
        : "=r"(r[0]), "=r"(r[1]), "=r"(r[2]), "=r"(r[3]) : "r"(a));
}
__device__ __forceinline__ void ldsm_x4t(uint32_t* r, uint32_t a) {
    asm volatile("ldmatrix.sync.aligned.m8n8.x4.trans.shared.b16 {%0,%1,%2,%3}, [%4];"
        : "=r"(r[0]), "=r"(r[1]), "=r"(r[2]), "=r"(r[3]) : "r"(a));
}
__device__ __forceinline__ void mma_f16(float* c, const uint32_t* a, const uint32_t* b) {
    asm volatile(
        "mma.sync.aligned.m16n8k16.row.col.f32.f16.f16.f32 "
        "{%0,%1,%2,%3}, {%4,%5,%6,%7}, {%8,%9}, {%0,%1,%2,%3};"
        : "+f"(c[0]), "+f"(c[1]), "+f"(c[2]), "+f"(c[3])
        : "r"(a[0]), "r"(a[1]), "r"(a[2]), "r"(a[3]), "r"(b[0]), "r"(b[1]));
}
// full split: x = hi + lo (fp16 each), packed pairs
__device__ __forceinline__ void hilo_h(float x0, float x1, uint32_t& h, uint32_t& l) {
    __half2 hh = __floats2half2_rn(x0, x1);
    float h0 = __low2float(hh), h1 = __high2float(hh);
    __half2 ll = __floats2half2_rn(x0 - h0, x1 - h1);
    h = *reinterpret_cast<uint32_t*>(&hh);
    l = *reinterpret_cast<uint32_t*>(&ll);
}
__device__ __forceinline__ uint32_t pack_h(float x0, float x1) {
    __half2 hh = __floats2half2_rn(x0, x1);
    return *reinterpret_cast<uint32_t*>(&hh);
}
__device__ __forceinline__ bool is_masked(const void* mask, int row) {
    int kind = g_mask_kind;
    if (kind == 1) return ((const unsigned char*)mask)[row] != 0;
    if (kind == 2) return ((const float*)mask)[row] != 0.0f;
    return ((const int*)mask)[row] != 0;
}

// ============================ Kernel 0: mask dtype sniff ============================
__global__ void k_detect(const unsigned int* __restrict__ m) {
    __shared__ int s_u8, s_f;
    if (threadIdx.x == 0) { s_u8 = 0; s_f = 0; }
    __syncthreads();
    for (int i = threadIdx.x; i < 8192; i += 256) {
        unsigned v = m[i];
        if (v == 0x3F800000u)      s_f  = 1;
        else if (v > 1u)           s_u8 = 1;
    }
    __syncthreads();
    if (threadIdx.x == 0) g_mask_kind = s_u8 ? 1 : (s_f ? 2 : 0);
}

// ============================ Kernel 1: K row norms (scaled by 256) ============================
__global__ void k_knorm(const float* __restrict__ k) {
    int row  = blockIdx.x * 8 + (threadIdx.x >> 5);
    int lane = threadIdx.x & 31;
    const float4* k4 = (const float4*)(k + (size_t)row * DD);
    float sb = 0.f;
#pragma unroll
    for (int j = 0; j < 2; j++) {
        float4 b = k4[lane + 32 * j];
        sb += b.x*b.x + b.y*b.y + b.z*b.z + b.w*b.w;
    }
#pragma unroll
    for (int o = 16; o; o >>= 1) sb += __shfl_xor_sync(0xFFFFFFFFu, sb, o);
    if (lane == 0) g_inv_b[row] = 256.0f / sb;   // x256: keeps fp16 lo normal
}

// ============================ Kernel 2: GEMM1 (fp16 2-pass split) ============================
__global__ void __launch_bounds__(256, 1)
k_g1(const float* __restrict__ K, const float* __restrict__ V) {
    extern __shared__ __align__(16) char sm[];
    const uint32_t sb = smem_u32(sm);
    const int tid = threadIdx.x, lane = tid & 31, wid = tid >> 5;
    const int b = blockIdx.z, split = blockIdx.y;
    const int m0 = (blockIdx.x >> 1) * 128, n0 = (blockIdx.x & 1) * 128;
    const float* Kb   = K + (size_t)b * SS * DD;
    const float* Vb   = V + (size_t)b * SS * DD;
    const float* invb = g_inv_b + b * SS;

    const int sl = tid >> 3, q0 = tid & 7;
    const int wm = (wid >> 2) * 64, wn = (wid & 3) * 32;
    const int rowT = (lane & 7) + ((lane >> 4) << 3);
    const int colT = ((lane >> 3) & 1) << 3;
    const int rowB = lane & 15;
    const int colB = (lane >> 4) << 3;

    float acc[4][4][4];
#pragma unroll
    for (int i = 0; i < 4; i++)
#pragma unroll
        for (int j = 0; j < 4; j++)
#pragma unroll
            for (int t = 0; t < 4; t++) acc[i][j][t] = 0.f;

    float4 rk[4], rv[4]; float ib;
    {
        int s = split * KSPLIT + sl;
        const float* kr = Kb + (size_t)s * DD + m0;
        const float* vr = Vb + (size_t)s * DD + n0;
        ib = invb[s];
#pragma unroll
        for (int j = 0; j < 4; j++) {
            rk[j] = *(const float4*)(kr + 4 * (q0 + 8 * j));
            rv[j] = *(const float4*)(vr + 4 * (q0 + 8 * j));
        }
    }
    {
        char* Ah = sm; char* Al = sm + BUFQ1; char* Bh = sm + 2*BUFQ1;
#pragma unroll
        for (int j = 0; j < 4; j++) {
            int off = sl * P1 + 8 * (q0 + 8 * j);
            uint32_t h01, l01, h23, l23;
            hilo_h(rk[j].x * ib, rk[j].y * ib, h01, l01);
            hilo_h(rk[j].z * ib, rk[j].w * ib, h23, l23);
            *(uint2*)(Ah + off) = make_uint2(h01, h23);
            *(uint2*)(Al + off) = make_uint2(l01, l23);
            *(uint2*)(Bh + off) = make_uint2(pack_h(rv[j].x, rv[j].y),
                                             pack_h(rv[j].z, rv[j].w));
        }
    }
    __syncthreads();

    for (int c = 0; c < NCH1; c++) {
        if (c + 1 < NCH1) {
            int s = split * KSPLIT + (c + 1) * 32 + sl;
            const float* kr = Kb + (size_t)s * DD + m0;
            const float* vr = Vb + (size_t)s * DD + n0;
            ib = invb[s];
#pragma unroll
            for (int j = 0; j < 4; j++) {
                rk[j] = *(const float4*)(kr + 4 * (q0 + 8 * j));
                rv[j] = *(const float4*)(vr + 4 * (q0 + 8 * j));
            }
        }
        const uint32_t ub = sb + (uint32_t)(c & 1) * BUF1;
        const uint32_t uAh = ub, uAl = ub + BUFQ1, uBh = ub + 2*BUFQ1;
#pragma unroll
        for (int ks = 0; ks < 32; ks += 16) {
            uint32_t ah[4][4], al[4][4], bh[4][2];
#pragma unroll
            for (int mf = 0; mf < 4; mf++) {
                uint32_t a = (uint32_t)((ks + rowT) * P1 + 2 * (wm + mf * 16 + colT));
                ldsm_x4t(ah[mf], uAh + a);
                ldsm_x4t(al[mf], uAl + a);
            }
#pragma unroll
            for (int nb = 0; nb < 2; nb++) {
                uint32_t a = (uint32_t)((ks + rowB) * P1 + 2 * (wn + nb * 16 + colB));
                ldsm_x4t(&bh[nb * 2][0], uBh + a);
            }
#pragma unroll
            for (int mi = 0; mi < 4; mi++)
#pragma unroll
                for (int ni = 0; ni < 4; ni++) {
                    mma_f16(acc[mi][ni], ah[mi], bh[ni]);
                    mma_f16(acc[mi][ni], al[mi], bh[ni]);
                }
        }
        if (c + 1 < NCH1) {
            char* bp = sm + ((c + 1) & 1) * BUF1;
            char* Ah = bp; char* Al = bp + BUFQ1; char* Bh = bp + 2*BUFQ1;
#pragma unroll
            for (int j = 0; j < 4; j++) {
                int off = sl * P1 + 8 * (q0 + 8 * j);
                uint32_t h01, l01, h23, l23;
                hilo_h(rk[j].x * ib, rk[j].y * ib, h01, l01);
                hilo_h(rk[j].z * ib, rk[j].w * ib, h23, l23);
                *(uint2*)(Ah + off) = make_uint2(h01, h23);
                *(uint2*)(Al + off) = make_uint2(l01, l23);
                *(uint2*)(Bh + off) = make_uint2(pack_h(rv[j].x, rv[j].y),
                                                 pack_h(rv[j].z, rv[j].w));
            }
        }
        __syncthreads();
    }

    float* out = g_s1p4[split] + (size_t)b * DD * DD;
    const int r0 = lane >> 2, cp = (lane & 3) * 2;
#pragma unroll
    for (int mi = 0; mi < 4; mi++)
#pragma unroll
        for (int ni = 0; ni < 4; ni++) {
            int m = m0 + wm + mi * 16 + r0;
            int n = n0 + wn + ni * 8 + cp;
            *(float2*)(out + (size_t)m * DD + n)       = make_float2(acc[mi][ni][0], acc[mi][ni][1]);
            *(float2*)(out + (size_t)(m + 8) * DD + n) = make_float2(acc[mi][ni][2], acc[mi][ni][3]);
        }
}

// ============================ Kernel 3: reduce partials (+ exact /256 unscale) ============================
__global__ void k_reduce() {
    int i = blockIdx.x * 256 + threadIdx.x;
    float4 a = ((const float4*)g_s1p4[0])[i];
    float4 b = ((const float4*)g_s1p4[1])[i];
    float4 c = ((const float4*)g_s1p4[2])[i];
    float4 d = ((const float4*)g_s1p4[3])[i];
    const float r = 1.0f / 256.0f;
    ((float4*)g_s1)[i] = make_float4((a.x+b.x+c.x+d.x)*r, (a.y+b.y+c.y+d.y)*r,
                                     (a.z+b.z+c.z+d.z)*r, (a.w+b.w+c.w+d.w)*r);
}

// ============================ Kernel 4: GEMM2 (fp16 2-pass, fused q-norm + mask) ============================
__global__ void __launch_bounds__(256, 1)
k_g2(const float* __restrict__ Q, const void* __restrict__ mask,
     float* __restrict__ Out) {
    extern __shared__ __align__(16) char sm[];
    const uint32_t sb = smem_u32(sm);
    const int tid = threadIdx.x, lane = tid & 31, wid = tid >> 5;
    const int b = blockIdx.z, m0 = blockIdx.y * 128, n0 = blockIdx.x * 128;
    const float* Qb  = Q + (size_t)b * SS * DD;
    const float* s1b = g_s1 + (size_t)b * DD * DD;
    float* smul = (float*)(sm + 2 * BUF2);

    const int ar = tid >> 1, aq0 = tid & 1;
    const int blr = tid >> 3, bq0 = tid & 7;
    const int wm = (wid >> 2) * 64, wn = (wid & 3) * 32;
    const int rowA = lane & 15, colA = (lane >> 4) << 3;
    const int rowB = lane & 15, colB = (lane >> 4) << 3;

    float acc[4][4][4];
#pragma unroll
    for (int i = 0; i < 4; i++)
#pragma unroll
        for (int j = 0; j < 4; j++)
#pragma unroll
            for (int t = 0; t < 4; t++) acc[i][j][t] = 0.f;

    // masked rows: A row := 1.0 so the GEMM computes colsum(s1) for free
    const bool msk = is_masked(mask, b * SS + m0 + ar);
    float qss = 0.f;
    float4 ra[4], rb[4];
    {
        const float* qr = Qb + (size_t)(m0 + ar) * DD;
#pragma unroll
        for (int j = 0; j < 4; j++) {
            ra[j] = *(const float4*)(qr + 4 * (aq0 + 2 * j));
            qss += ra[j].x*ra[j].x + ra[j].y*ra[j].y + ra[j].z*ra[j].z + ra[j].w*ra[j].w;
            if (msk) ra[j] = make_float4(1.f, 1.f, 1.f, 1.f);
            rb[j] = *(const float4*)(s1b + (size_t)blr * DD + n0 + 4 * (bq0 + 8 * j));
        }
    }
    {
        char* Ah = sm; char* Al = sm + A2SZ; char* Bh = sm + 2*A2SZ;
#pragma unroll
        for (int j = 0; j < 4; j++) {
            int off = ar * P2 + 8 * (aq0 + 2 * j);
            uint32_t h01, l01, h23, l23;
            hilo_h(ra[j].x, ra[j].y, h01, l01);
            hilo_h(ra[j].z, ra[j].w, h23, l23);
            *(uint2*)(Ah + off) = make_uint2(h01, h23);
            *(uint2*)(Al + off) = make_uint2(l01, l23);
            int offb = blr * P1 + 8 * (bq0 + 8 * j);
            *(uint2*)(Bh + offb) = make_uint2(pack_h(rb[j].x, rb[j].y),
                                              pack_h(rb[j].z, rb[j].w));
        }
    }
    __syncthreads();

    for (int c = 0; c < NCH2; c++) {
        if (c + 1 < NCH2) {
            int k0 = (c + 1) * 32;
            const float* qr = Qb + (size_t)(m0 + ar) * DD + k0;
#pragma unroll
            for (int j = 0; j < 4; j++) {
                ra[j] = *(const float4*)(qr + 4 * (aq0 + 2 * j));
                qss += ra[j].x*ra[j].x + ra[j].y*ra[j].y + ra[j].z*ra[j].z + ra[j].w*ra[j].w;
                if (msk) ra[j] = make_float4(1.f, 1.f, 1.f, 1.f);
                rb[j] = *(const float4*)(s1b + (size_t)(k0 + blr) * DD + n0 + 4 * (bq0 + 8 * j));
            }
        }
        const uint32_t ub = sb + (uint32_t)(c & 1) * BUF2;
        const uint32_t uAh = ub, uAl = ub + A2SZ, uBh = ub + 2*A2SZ;
#pragma unroll
        for (int ks = 0; ks < 32; ks += 16) {
            uint32_t ah[4][4], al[4][4], bh[4][2];
#pragma unroll
            for (int mf = 0; mf < 4; mf++) {
                uint32_t a = (uint32_t)((wm + mf * 16 + rowA) * P2 + 2 * (ks + colA));
                ldsm_x4(ah[mf], uAh + a);
                ldsm_x4(al[mf], uAl + a);
            }
#pragma unroll
            for (int nb = 0; nb < 2; nb++) {
                uint32_t a = (uint32_t)((ks + rowB) * P1 + 2 * (wn + nb * 16 + colB));
                ldsm_x4t(&bh[nb * 2][0], uBh + a);
            }
#pragma unroll
            for (int mi = 0; mi < 4; mi++)
#pragma unroll
                for (int ni = 0; ni < 4; ni++) {
                    mma_f16(acc[mi][ni], ah[mi], bh[ni]);
                    mma_f16(acc[mi][ni], al[mi], bh[ni]);
                }
        }
        if (c + 1 < NCH2) {
            char* bp = sm + ((c + 1) & 1) * BUF2;
            char* Ah = bp; char* Al = bp + A2SZ; char* Bh = bp + 2*A2SZ;
#pragma unroll
            for (int j = 0; j < 4; j++) {
                int off = ar * P2 + 8 * (aq0 + 2 * j);
                uint32_t h01, l01, h23, l23;
                hilo_h(ra[j].x, ra[j].y, h01, l01);
                hilo_h(ra[j].z, ra[j].w, h23, l23);
                *(uint2*)(Ah + off) = make_uint2(h01, h23);
                *(uint2*)(Al + off) = make_uint2(l01, l23);
                int offb = blr * P1 + 8 * (bq0 + 8 * j);
                *(uint2*)(Bh + offb) = make_uint2(pack_h(rb[j].x, rb[j].y),
                                                  pack_h(rb[j].z, rb[j].w));
            }
        }
        __syncthreads();
    }

    qss += __shfl_xor_sync(0xFFFFFFFFu, qss, 1);
    if (aq0 == 0) smul[ar] = msk ? 0.0f : 1.0f / qss;
    __syncthreads();

    const float sc = 1.0f / 256.0f;
    const int r0 = lane >> 2, cp = (lane & 3) * 2;
#pragma unroll
    for (int mi = 0; mi < 4; mi++) {
        int m1 = m0 + wm + mi * 16 + r0;
        int m2 = m1 + 8;
        float mu1 = smul[m1 - m0], mu2 = smul[m2 - m0];
        float s1f = (mu1 == 0.0f) ? (NEGV * sc) : mu1 * sc;
        float s2f = (mu2 == 0.0f) ? (NEGV * sc) : mu2 * sc;
        float* o1 = Out + ((size_t)b * SS + m1) * DD;
        float* o2 = Out + ((size_t)b * SS + m2) * DD;
#pragma unroll
        for (int ni = 0; ni < 4; ni++) {
            int n = n0 + wn + ni * 8 + cp;
            *(float2*)(o1 + n) = make_float2(acc[mi][ni][0] * s1f, acc[mi][ni][1] * s1f);
            *(float2*)(o2 + n) = make_float2(acc[mi][ni][2] * s2f, acc[mi][ni][3] * s2f);
        }
    }
}

// ===========================================================================
extern "C" void kernel_launch(void* const* d_in, const int* in_sizes, int n_in,
                              void* d_out, int out_size) {
    const float* q    = (const float*)d_in[0];
    const float* k    = (const float*)d_in[1];
    const float* v    = (const float*)d_in[2];
    const void*  mask = d_in[3];
    float* out = (float*)d_out;

    const int SMEM_G1 = 2 * BUF1;         // 52224
    const int SMEM_G2 = 2 * BUF2 + 512;   // 58880
    cudaFuncSetAttribute(k_g1, cudaFuncAttributeMaxDynamicSharedMemorySize, SMEM_G1);
    cudaFuncSetAttribute(k_g2, cudaFuncAttributeMaxDynamicSharedMemorySize, SMEM_G2);

    k_detect<<<1, 256>>>((const unsigned int*)mask);
    k_knorm<<<NROWS / 8, 256>>>(k);
    k_g1<<<dim3(4, NSPLIT, BB), 256, SMEM_G1>>>(k, v);
    k_reduce<<<(BB * DD * DD / 4) / 256, 256>>>();
    k_g2<<<dim3(2, SS / 128, BB), 256, SMEM_G2>>>(q, mask, out);
}

// round 7
// speedup vs baseline: 1.3595x; 1.1562x over previous
#include <cuda_runtime.h>
#include <cuda_fp16.h>
#include <cstdint>

#define BB 8
#define SS 4096
#define DD 256
#define NROWS (BB*SS)
#define NEGV  (-1000000000.0f)
#define NSPLIT 4
#define KSPLIT (SS/NSPLIT)   // 1024
#define NCH1 (KSPLIT/32)     // 32
#define NCH2 (DD/32)         // 8
#define P1 272
#define P2 80
#define BUFQ1 (32*P1)        // 8704
#define BUF1  (3*BUFQ1)      // 26112  (Ah,Al,Bh)
#define A2SZ  (128*P2)       // 10240
#define BUF2  (2*A2SZ + 32*P1)   // 29184 (Ah,Al,Bh)

// ---- scratch ----
__device__ float g_inv_b[NROWS];
__device__ float g_s1[BB*DD*DD];
__device__ float g_s1p4[NSPLIT][BB*DD*DD];
__device__ int   g_mask_kind;

// ============================ helpers ============================
__device__ __forceinline__ uint32_t smem_u32(const void* p) {
    uint32_t a;
    asm("{ .reg .u64 t; cvta.to.shared.u64 t, %1; cvt.u32.u64 %0, t; }"
        : "=r"(a) : "l"(p));
    return a;
}
__device__ __forceinline__ void ldsm_x4(uint32_t* r, uint32_t a) {
    asm volatile("ldmatrix.sync.aligned.m8n8.x4.shared.b16 {%0,%1,%2,%3}, [%4];"
        : "=r"(r[0]), "=r"(r[1]), "=r"(r[2]), "=r"(r[3]) : "r"(a));
}
__device__ __forceinline__ void ldsm_x4t(uint32_t* r, uint32_t a) {
    asm volatile("ldmatrix.sync.aligned.m8n8.x4.trans.shared.b16 {%0,%1,%2,%3}, [%4];"
        : "=r"(r[0]), "=r"(r[1]), "=r"(r[2]), "=r"(r[3]) : "r"(a));
}
__device__ __forceinline__ void mma_f16(float* c, const uint32_t* a, const uint32_t* b) {
    asm volatile(
        "mma.sync.aligned.m16n8k16.row.col.f32.f16.f16.f32 "
        "{%0,%1,%2,%3}, {%4,%5,%6,%7}, {%8,%9}, {%0,%1,%2,%3};"
        : "+f"(c[0]), "+f"(c[1]), "+f"(c[2]), "+f"(c[3])
        : "r"(a[0]), "r"(a[1]), "r"(a[2]), "r"(a[3]), "r"(b[0]), "r"(b[1]));
}
__device__ __forceinline__ void hilo_h(float x0, float x1, uint32_t& h, uint32_t& l) {
    __half2 hh = __floats2half2_rn(x0, x1);
    float h0 = __low2float(hh), h1 = __high2float(hh);
    __half2 ll = __floats2half2_rn(x0 - h0, x1 - h1);
    h = *reinterpret_cast<uint32_t*>(&hh);
    l = *reinterpret_cast<uint32_t*>(&ll);
}
__device__ __forceinline__ uint32_t pack_h(float x0, float x1) {
    __half2 hh = __floats2half2_rn(x0, x1);
    return *reinterpret_cast<uint32_t*>(&hh);
}
__device__ __forceinline__ bool is_masked(const void* mask, int row) {
    int kind = g_mask_kind;
    if (kind == 1) return ((const unsigned char*)mask)[row] != 0;
    if (kind == 2) return ((const float*)mask)[row] != 0.0f;
    return ((const int*)mask)[row] != 0;
}

// ============================ Kernel 1: K row norms + (block 0) mask sniff ============================
__global__ void k_knorm(const float* __restrict__ k, const unsigned int* __restrict__ m) {
    if (blockIdx.x == 0) {           // fused mask-dtype detection
        __shared__ int s_u8, s_f;
        if (threadIdx.x == 0) { s_u8 = 0; s_f = 0; }
        __syncthreads();
        for (int i = threadIdx.x; i < 8192; i += 256) {
            unsigned v = m[i];
            if (v == 0x3F800000u)      s_f  = 1;
            else if (v > 1u)           s_u8 = 1;
        }
        __syncthreads();
        if (threadIdx.x == 0) g_mask_kind = s_u8 ? 1 : (s_f ? 2 : 0);
    }
    int row  = blockIdx.x * 8 + (threadIdx.x >> 5);
    int lane = threadIdx.x & 31;
    const float4* k4 = (const float4*)(k + (size_t)row * DD);
    float sb = 0.f;
#pragma unroll
    for (int j = 0; j < 2; j++) {
        float4 b = k4[lane + 32 * j];
        sb += b.x*b.x + b.y*b.y + b.z*b.z + b.w*b.w;
    }
#pragma unroll
    for (int o = 16; o; o >>= 1) sb += __shfl_xor_sync(0xFFFFFFFFu, sb, o);
    if (lane == 0) g_inv_b[row] = 256.0f / sb;   // x256: keeps fp16 lo normal
}

// ============================ Kernel 2: GEMM1 (fp16 2-pass split, occ 2) ============================
__global__ void __launch_bounds__(256, 2)
k_g1(const float* __restrict__ K, const float* __restrict__ V) {
    extern __shared__ __align__(16) char sm[];
    const uint32_t sb = smem_u32(sm);
    const int tid = threadIdx.x, lane = tid & 31, wid = tid >> 5;
    const int b = blockIdx.z, split = blockIdx.y;
    const int m0 = (blockIdx.x >> 1) * 128, n0 = (blockIdx.x & 1) * 128;
    const float* Kb   = K + (size_t)b * SS * DD;
    const float* Vb   = V + (size_t)b * SS * DD;
    const float* invb = g_inv_b + b * SS;

    const int sl = tid >> 3, q0 = tid & 7;
    const int wm = (wid >> 2) * 64, wn = (wid & 3) * 32;
    const int rowT = (lane & 7) + ((lane >> 4) << 3);
    const int colT = ((lane >> 3) & 1) << 3;
    const int rowB = lane & 15;
    const int colB = (lane >> 4) << 3;

    float acc[4][4][4];
#pragma unroll
    for (int i = 0; i < 4; i++)
#pragma unroll
        for (int j = 0; j < 4; j++)
#pragma unroll
            for (int t = 0; t < 4; t++) acc[i][j][t] = 0.f;

    float4 rk[4], rv[4]; float ib;
    {
        int s = split * KSPLIT + sl;
        const float* kr = Kb + (size_t)s * DD + m0;
        const float* vr = Vb + (size_t)s * DD + n0;
        ib = invb[s];
#pragma unroll
        for (int j = 0; j < 4; j++) {
            rk[j] = *(const float4*)(kr + 4 * (q0 + 8 * j));
            rv[j] = *(const float4*)(vr + 4 * (q0 + 8 * j));
        }
    }
    {
        char* Ah = sm; char* Al = sm + BUFQ1; char* Bh = sm + 2*BUFQ1;
#pragma unroll
        for (int j = 0; j < 4; j++) {
            int off = sl * P1 + 8 * (q0 + 8 * j);
            uint32_t h01, l01, h23, l23;
            hilo_h(rk[j].x * ib, rk[j].y * ib, h01, l01);
            hilo_h(rk[j].z * ib, rk[j].w * ib, h23, l23);
            *(uint2*)(Ah + off) = make_uint2(h01, h23);
            *(uint2*)(Al + off) = make_uint2(l01, l23);
            *(uint2*)(Bh + off) = make_uint2(pack_h(rv[j].x, rv[j].y),
                                             pack_h(rv[j].z, rv[j].w));
        }
    }
    __syncthreads();

    for (int c = 0; c < NCH1; c++) {
        if (c + 1 < NCH1) {
            int s = split * KSPLIT + (c + 1) * 32 + sl;
            const float* kr = Kb + (size_t)s * DD + m0;
            const float* vr = Vb + (size_t)s * DD + n0;
            ib = invb[s];
#pragma unroll
            for (int j = 0; j < 4; j++) {
                rk[j] = *(const float4*)(kr + 4 * (q0 + 8 * j));
                rv[j] = *(const float4*)(vr + 4 * (q0 + 8 * j));
            }
        }
        const uint32_t ub = sb + (uint32_t)(c & 1) * BUF1;
        const uint32_t uAh = ub, uAl = ub + BUFQ1, uBh = ub + 2*BUFQ1;
#pragma unroll
        for (int ks = 0; ks < 32; ks += 16) {
            uint32_t ah[4][4], al[4][4], bh[4][2];
#pragma unroll
            for (int mf = 0; mf < 4; mf++) {
                uint32_t a = (uint32_t)((ks + rowT) * P1 + 2 * (wm + mf * 16 + colT));
                ldsm_x4t(ah[mf], uAh + a);
                ldsm_x4t(al[mf], uAl + a);
            }
#pragma unroll
            for (int nb = 0; nb < 2; nb++) {
                uint32_t a = (uint32_t)((ks + rowB) * P1 + 2 * (wn + nb * 16 + colB));
                ldsm_x4t(&bh[nb * 2][0], uBh + a);
            }
#pragma unroll
            for (int mi = 0; mi < 4; mi++)
#pragma unroll
                for (int ni = 0; ni < 4; ni++) {
                    mma_f16(acc[mi][ni], ah[mi], bh[ni]);
                    mma_f16(acc[mi][ni], al[mi], bh[ni]);
                }
        }
        if (c + 1 < NCH1) {
            char* bp = sm + ((c + 1) & 1) * BUF1;
            char* Ah = bp; char* Al = bp + BUFQ1; char* Bh = bp + 2*BUFQ1;
#pragma unroll
            for (int j = 0; j < 4; j++) {
                int off = sl * P1 + 8 * (q0 + 8 * j);
                uint32_t h01, l01, h23, l23;
                hilo_h(rk[j].x * ib, rk[j].y * ib, h01, l01);
                hilo_h(rk[j].z * ib, rk[j].w * ib, h23, l23);
                *(uint2*)(Ah + off) = make_uint2(h01, h23);
                *(uint2*)(Al + off) = make_uint2(l01, l23);
                *(uint2*)(Bh + off) = make_uint2(pack_h(rv[j].x, rv[j].y),
                                                 pack_h(rv[j].z, rv[j].w));
            }
        }
        __syncthreads();
    }

    float* out = g_s1p4[split] + (size_t)b * DD * DD;
    const int r0 = lane >> 2, cp = (lane & 3) * 2;
#pragma unroll
    for (int mi = 0; mi < 4; mi++)
#pragma unroll
        for (int ni = 0; ni < 4; ni++) {
            int m = m0 + wm + mi * 16 + r0;
            int n = n0 + wn + ni * 8 + cp;
            *(float2*)(out + (size_t)m * DD + n)       = make_float2(acc[mi][ni][0], acc[mi][ni][1]);
            *(float2*)(out + (size_t)(m + 8) * DD + n) = make_float2(acc[mi][ni][2], acc[mi][ni][3]);
        }
}

// ============================ Kernel 3: reduce partials (ILP x2, exact /256) ============================
__global__ void k_reduce() {
    int i0 = blockIdx.x * 512 + threadIdx.x;
    const float r = 1.0f / 256.0f;
#pragma unroll
    for (int u = 0; u < 2; u++) {
        int i = i0 + u * 256;
        float4 a = ((const float4*)g_s1p4[0])[i];
        float4 b = ((const float4*)g_s1p4[1])[i];
        float4 c = ((const float4*)g_s1p4[2])[i];
        float4 d = ((const float4*)g_s1p4[3])[i];
        ((float4*)g_s1)[i] = make_float4((a.x+b.x+c.x+d.x)*r, (a.y+b.y+c.y+d.y)*r,
                                         (a.z+b.z+c.z+d.z)*r, (a.w+b.w+c.w+d.w)*r);
    }
}

// ============================ Kernel 4: GEMM2 (fp16 2-pass, fused q-norm + mask, occ 2) ============================
__global__ void __launch_bounds__(256, 2)
k_g2(const float* __restrict__ Q, const void* __restrict__ mask,
     float* __restrict__ Out) {
    extern __shared__ __align__(16) char sm[];
    const uint32_t sb = smem_u32(sm);
    const int tid = threadIdx.x, lane = tid & 31, wid = tid >> 5;
    const int b = blockIdx.z, m0 = blockIdx.y * 128, n0 = blockIdx.x * 128;
    const float* Qb  = Q + (size_t)b * SS * DD;
    const float* s1b = g_s1 + (size_t)b * DD * DD;
    float* smul = (float*)(sm + 2 * BUF2);

    const int ar = tid >> 1, aq0 = tid & 1;
    const int blr = tid >> 3, bq0 = tid & 7;
    const int wm = (wid >> 2) * 64, wn = (wid & 3) * 32;
    const int rowA = lane & 15, colA = (lane >> 4) << 3;
    const int rowB = lane & 15, colB = (lane >> 4) << 3;

    float acc[4][4][4];
#pragma unroll
    for (int i = 0; i < 4; i++)
#pragma unroll
        for (int j = 0; j < 4; j++)
#pragma unroll
            for (int t = 0; t < 4; t++) acc[i][j][t] = 0.f;

    const bool msk = is_masked(mask, b * SS + m0 + ar);
    float qss = 0.f;
    float4 ra[4], rb[4];
    {
        const float* qr = Qb + (size_t)(m0 + ar) * DD;
#pragma unroll
        for (int j = 0; j < 4; j++) {
            ra[j] = *(const float4*)(qr + 4 * (aq0 + 2 * j));
            qss += ra[j].x*ra[j].x + ra[j].y*ra[j].y + ra[j].z*ra[j].z + ra[j].w*ra[j].w;
            if (msk) ra[j] = make_float4(1.f, 1.f, 1.f, 1.f);
            rb[j] = *(const float4*)(s1b + (size_t)blr * DD + n0 + 4 * (bq0 + 8 * j));
        }
    }
    {
        char* Ah = sm; char* Al = sm + A2SZ; char* Bh = sm + 2*A2SZ;
#pragma unroll
        for (int j = 0; j < 4; j++) {
            int off = ar * P2 + 8 * (aq0 + 2 * j);
            uint32_t h01, l01, h23, l23;
            hilo_h(ra[j].x, ra[j].y, h01, l01);
            hilo_h(ra[j].z, ra[j].w, h23, l23);
            *(uint2*)(Ah + off) = make_uint2(h01, h23);
            *(uint2*)(Al + off) = make_uint2(l01, l23);
            int offb = blr * P1 + 8 * (bq0 + 8 * j);
            *(uint2*)(Bh + offb) = make_uint2(pack_h(rb[j].x, rb[j].y),
                                              pack_h(rb[j].z, rb[j].w));
        }
    }
    __syncthreads();

    for (int c = 0; c < NCH2; c++) {
        if (c + 1 < NCH2) {
            int k0 = (c + 1) * 32;
            const float* qr = Qb + (size_t)(m0 + ar) * DD + k0;
#pragma unroll
            for (int j = 0; j < 4; j++) {
                ra[j] = *(const float4*)(qr + 4 * (aq0 + 2 * j));
                qss += ra[j].x*ra[j].x + ra[j].y*ra[j].y + ra[j].z*ra[j].z + ra[j].w*ra[j].w;
                if (msk) ra[j] = make_float4(1.f, 1.f, 1.f, 1.f);
                rb[j] = *(const float4*)(s1b + (size_t)(k0 + blr) * DD + n0 + 4 * (bq0 + 8 * j));
            }
        }
        const uint32_t ub = sb + (uint32_t)(c & 1) * BUF2;
        const uint32_t uAh = ub, uAl = ub + A2SZ, uBh = ub + 2*A2SZ;
#pragma unroll
        for (int ks = 0; ks < 32; ks += 16) {
            uint32_t ah[4][4], al[4][4], bh[4][2];
#pragma unroll
            for (int mf = 0; mf < 4; mf++) {
                uint32_t a = (uint32_t)((wm + mf * 16 + rowA) * P2 + 2 * (ks + colA));
                ldsm_x4(ah[mf], uAh + a);
                ldsm_x4(al[mf], uAl + a);
            }
#pragma unroll
            for (int nb = 0; nb < 2; nb++) {
                uint32_t a = (uint32_t)((ks + rowB) * P1 + 2 * (wn + nb * 16 + colB));
                ldsm_x4t(&bh[nb * 2][0], uBh + a);
            }
#pragma unroll
            for (int mi = 0; mi < 4; mi++)
#pragma unroll
                for (int ni = 0; ni < 4; ni++) {
                    mma_f16(acc[mi][ni], ah[mi], bh[ni]);
                    mma_f16(acc[mi][ni], al[mi], bh[ni]);
                }
        }
        if (c + 1 < NCH2) {
            char* bp = sm + ((c + 1) & 1) * BUF2;
            char* Ah = bp; char* Al = bp + A2SZ; char* Bh = bp + 2*A2SZ;
#pragma unroll
            for (int j = 0; j < 4; j++) {
                int off = ar * P2 + 8 * (aq0 + 2 * j);
                uint32_t h01, l01, h23, l23;
                hilo_h(ra[j].x, ra[j].y, h01, l01);
                hilo_h(ra[j].z, ra[j].w, h23, l23);
                *(uint2*)(Ah + off) = make_uint2(h01, h23);
                *(uint2*)(Al + off) = make_uint2(l01, l23);
                int offb = blr * P1 + 8 * (bq0 + 8 * j);
                *(uint2*)(Bh + offb) = make_uint2(pack_h(rb[j].x, rb[j].y),
                                                  pack_h(rb[j].z, rb[j].w));
            }
        }
        __syncthreads();
    }

    qss += __shfl_xor_sync(0xFFFFFFFFu, qss, 1);
    if (aq0 == 0) smul[ar] = msk ? 0.0f : 1.0f / qss;
    __syncthreads();

    const float sc = 1.0f / 256.0f;
    const int r0 = lane >> 2, cp = (lane & 3) * 2;
#pragma unroll
    for (int mi = 0; mi < 4; mi++) {
        int m1 = m0 + wm + mi * 16 + r0;
        int m2 = m1 + 8;
        float mu1 = smul[m1 - m0], mu2 = smul[m2 - m0];
        float s1f = (mu1 == 0.0f) ? (NEGV * sc) : mu1 * sc;
        float s2f = (mu2 == 0.0f) ? (NEGV * sc) : mu2 * sc;
        float* o1 = Out + ((size_t)b * SS + m1) * DD;
        float* o2 = Out + ((size_t)b * SS + m2) * DD;
#pragma unroll
        for (int ni = 0; ni < 4; ni++) {
            int n = n0 + wn + ni * 8 + cp;
            *(float2*)(o1 + n) = make_float2(acc[mi][ni][0] * s1f, acc[mi][ni][1] * s1f);
            *(float2*)(o2 + n) = make_float2(acc[mi][ni][2] * s2f, acc[mi][ni][3] * s2f);
        }
    }
}

// ===========================================================================
extern "C" void kernel_launch(void* const* d_in, const int* in_sizes, int n_in,
                              void* d_out, int out_size) {
    const float* q    = (const float*)d_in[0];
    const float* k    = (const float*)d_in[1];
    const float* v    = (const float*)d_in[2];
    const void*  mask = d_in[3];
    float* out = (float*)d_out;

    const int SMEM_G1 = 2 * BUF1;         // 52224
    const int SMEM_G2 = 2 * BUF2 + 512;   // 58880
    cudaFuncSetAttribute(k_g1, cudaFuncAttributeMaxDynamicSharedMemorySize, SMEM_G1);
    cudaFuncSetAttribute(k_g2, cudaFuncAttributeMaxDynamicSharedMemorySize, SMEM_G2);

    k_knorm<<<NROWS / 8, 256>>>(k, (const unsigned int*)mask);
    k_g1<<<dim3(4, NSPLIT, BB), 256, SMEM_G1>>>(k, v);
    k_reduce<<<(BB * DD * DD / 8) / 256, 256>>>();
    k_g2<<<dim3(2, SS / 128, BB), 256, SMEM_G2>>>(q, mask, out);
}

// round 8
// speedup vs baseline: 1.7682x; 1.3007x over previous
#include <cuda_runtime.h>
#include <cuda_fp16.h>
#include <cstdint>

#define BB 8
#define SS 4096
#define DD 256
#define NROWS (BB*SS)
#define NEGV  (-1000000000.0f)
#define NSPLIT 8
#define KSPLIT (SS/NSPLIT)   // 512
#define NCH1 (KSPLIT/32)     // 16
#define NCH2 (DD/32)         // 8
#define P1 272
#define P2 80
#define BUFQ1 (32*P1)        // 8704
#define BUF1  (2*BUFQ1)      // 17408  (Ah,Bh)
#define A2SZ  (128*P2)       // 10240
#define BUF2  (A2SZ + 32*P1) // 18944  (Ah,Bh)

// ---- scratch ----
__device__ float g_inv_b[NROWS];
__device__ float g_s1[BB*DD*DD];
__device__ float g_s1p[NSPLIT][BB*DD*DD];
__device__ int   g_mask_kind;

// ============================ helpers ============================
__device__ __forceinline__ uint32_t smem_u32(const void* p) {
    uint32_t a;
    asm("{ .reg .u64 t; cvta.to.shared.u64 t, %1; cvt.u32.u64 %0, t; }"
        : "=r"(a) : "l"(p));
    return a;
}
__device__ __forceinline__ void ldsm_x4(uint32_t* r, uint32_t a) {
    asm volatile("ldmatrix.sync.aligned.m8n8.x4.shared.b16 {%0,%1,%2,%3}, [%4];"
        : "=r"(r[0]), "=r"(r[1]), "=r"(r[2]), "=r"(r[3]) : "r"(a));
}
__device__ __forceinline__ void ldsm_x4t(uint32_t* r, uint32_t a) {
    asm volatile("ldmatrix.sync.aligned.m8n8.x4.trans.shared.b16 {%0,%1,%2,%3}, [%4];"
        : "=r"(r[0]), "=r"(r[1]), "=r"(r[2]), "=r"(r[3]) : "r"(a));
}
__device__ __forceinline__ void mma_f16(float* c, const uint32_t* a, const uint32_t* b) {
    asm volatile(
        "mma.sync.aligned.m16n8k16.row.col.f32.f16.f16.f32 "
        "{%0,%1,%2,%3}, {%4,%5,%6,%7}, {%8,%9}, {%0,%1,%2,%3};"
        : "+f"(c[0]), "+f"(c[1]), "+f"(c[2]), "+f"(c[3])
        : "r"(a[0]), "r"(a[1]), "r"(a[2]), "r"(a[3]), "r"(b[0]), "r"(b[1]));
}
__device__ __forceinline__ uint32_t pack_h(float x0, float x1) {
    __half2 hh = __floats2half2_rn(x0, x1);
    return *reinterpret_cast<uint32_t*>(&hh);
}
__device__ __forceinline__ bool is_masked(const void* mask, int row) {
    int kind = g_mask_kind;
    if (kind == 1) return ((const unsigned char*)mask)[row] != 0;
    if (kind == 2) return ((const float*)mask)[row] != 0.0f;
    return ((const int*)mask)[row] != 0;
}

// ============================ Kernel 1: K row norms + (block 0) mask sniff ============================
__global__ void k_knorm(const float* __restrict__ k, const unsigned int* __restrict__ m) {
    if (blockIdx.x == 0) {
        __shared__ int s_u8, s_f;
        if (threadIdx.x == 0) { s_u8 = 0; s_f = 0; }
        __syncthreads();
        for (int i = threadIdx.x; i < 8192; i += 256) {
            unsigned v = m[i];
            if (v == 0x3F800000u)      s_f  = 1;
            else if (v > 1u)           s_u8 = 1;
        }
        __syncthreads();
        if (threadIdx.x == 0) g_mask_kind = s_u8 ? 1 : (s_f ? 2 : 0);
    }
    int row  = blockIdx.x * 8 + (threadIdx.x >> 5);
    int lane = threadIdx.x & 31;
    const float4* k4 = (const float4*)(k + (size_t)row * DD);
    float sb = 0.f;
#pragma unroll
    for (int j = 0; j < 2; j++) {
        float4 b = k4[lane + 32 * j];
        sb += b.x*b.x + b.y*b.y + b.z*b.z + b.w*b.w;
    }
#pragma unroll
    for (int o = 16; o; o >>= 1) sb += __shfl_xor_sync(0xFFFFFFFFu, sb, o);
    if (lane == 0) g_inv_b[row] = 256.0f / sb;   // x256: better fp16 range
}

// ============================ Kernel 2: GEMM1 (single-pass fp16, occ 2, split-K 8) ============================
__global__ void __launch_bounds__(256, 2)
k_g1(const float* __restrict__ K, const float* __restrict__ V) {
    extern __shared__ __align__(16) char sm[];
    const uint32_t sb = smem_u32(sm);
    const int tid = threadIdx.x, lane = tid & 31, wid = tid >> 5;
    const int b = blockIdx.z, split = blockIdx.y;
    const int m0 = (blockIdx.x >> 1) * 128, n0 = (blockIdx.x & 1) * 128;
    const float* Kb   = K + (size_t)b * SS * DD;
    const float* Vb   = V + (size_t)b * SS * DD;
    const float* invb = g_inv_b + b * SS;

    const int sl = tid >> 3, q0 = tid & 7;
    const int wm = (wid >> 2) * 64, wn = (wid & 3) * 32;
    const int rowT = (lane & 7) + ((lane >> 4) << 3);
    const int colT = ((lane >> 3) & 1) << 3;
    const int rowB = lane & 15;
    const int colB = (lane >> 4) << 3;

    float acc[4][4][4];
#pragma unroll
    for (int i = 0; i < 4; i++)
#pragma unroll
        for (int j = 0; j < 4; j++)
#pragma unroll
            for (int t = 0; t < 4; t++) acc[i][j][t] = 0.f;

    float4 rk[4], rv[4]; float ib;
    {
        int s = split * KSPLIT + sl;
        const float* kr = Kb + (size_t)s * DD + m0;
        const float* vr = Vb + (size_t)s * DD + n0;
        ib = invb[s];
#pragma unroll
        for (int j = 0; j < 4; j++) {
            rk[j] = *(const float4*)(kr + 4 * (q0 + 8 * j));
            rv[j] = *(const float4*)(vr + 4 * (q0 + 8 * j));
        }
    }
    {
        char* Ah = sm; char* Bh = sm + BUFQ1;
#pragma unroll
        for (int j = 0; j < 4; j++) {
            int off = sl * P1 + 8 * (q0 + 8 * j);
            *(uint2*)(Ah + off) = make_uint2(pack_h(rk[j].x * ib, rk[j].y * ib),
                                             pack_h(rk[j].z * ib, rk[j].w * ib));
            *(uint2*)(Bh + off) = make_uint2(pack_h(rv[j].x, rv[j].y),
                                             pack_h(rv[j].z, rv[j].w));
        }
    }
    __syncthreads();

    for (int c = 0; c < NCH1; c++) {
        if (c + 1 < NCH1) {
            int s = split * KSPLIT + (c + 1) * 32 + sl;
            const float* kr = Kb + (size_t)s * DD + m0;
            const float* vr = Vb + (size_t)s * DD + n0;
            ib = invb[s];
#pragma unroll
            for (int j = 0; j < 4; j++) {
                rk[j] = *(const float4*)(kr + 4 * (q0 + 8 * j));
                rv[j] = *(const float4*)(vr + 4 * (q0 + 8 * j));
            }
        }
        const uint32_t ub = sb + (uint32_t)(c & 1) * BUF1;
        const uint32_t uAh = ub, uBh = ub + BUFQ1;
#pragma unroll
        for (int ks = 0; ks < 32; ks += 16) {
            uint32_t ah[4][4], bh[4][2];
#pragma unroll
            for (int mf = 0; mf < 4; mf++) {
                uint32_t a = (uint32_t)((ks + rowT) * P1 + 2 * (wm + mf * 16 + colT));
                ldsm_x4t(ah[mf], uAh + a);
            }
#pragma unroll
            for (int nb = 0; nb < 2; nb++) {
                uint32_t a = (uint32_t)((ks + rowB) * P1 + 2 * (wn + nb * 16 + colB));
                ldsm_x4t(&bh[nb * 2][0], uBh + a);
            }
#pragma unroll
            for (int mi = 0; mi < 4; mi++)
#pragma unroll
                for (int ni = 0; ni < 4; ni++)
                    mma_f16(acc[mi][ni], ah[mi], bh[ni]);
        }
        if (c + 1 < NCH1) {
            char* bp = sm + ((c + 1) & 1) * BUF1;
            char* Ah = bp; char* Bh = bp + BUFQ1;
#pragma unroll
            for (int j = 0; j < 4; j++) {
                int off = sl * P1 + 8 * (q0 + 8 * j);
                *(uint2*)(Ah + off) = make_uint2(pack_h(rk[j].x * ib, rk[j].y * ib),
                                                 pack_h(rk[j].z * ib, rk[j].w * ib));
                *(uint2*)(Bh + off) = make_uint2(pack_h(rv[j].x, rv[j].y),
                                                 pack_h(rv[j].z, rv[j].w));
            }
        }
        __syncthreads();
    }

    float* out = g_s1p[split] + (size_t)b * DD * DD;
    const int r0 = lane >> 2, cp = (lane & 3) * 2;
#pragma unroll
    for (int mi = 0; mi < 4; mi++)
#pragma unroll
        for (int ni = 0; ni < 4; ni++) {
            int m = m0 + wm + mi * 16 + r0;
            int n = n0 + wn + ni * 8 + cp;
            *(float2*)(out + (size_t)m * DD + n)       = make_float2(acc[mi][ni][0], acc[mi][ni][1]);
            *(float2*)(out + (size_t)(m + 8) * DD + n) = make_float2(acc[mi][ni][2], acc[mi][ni][3]);
        }
}

// ============================ Kernel 3: reduce 8 partials (ILP x2, exact /256) ============================
__global__ void k_reduce() {
    int i0 = blockIdx.x * 512 + threadIdx.x;
    const float r = 1.0f / 256.0f;
#pragma unroll
    for (int u = 0; u < 2; u++) {
        int i = i0 + u * 256;
        float sx = 0.f, sy = 0.f, sz = 0.f, sw = 0.f;
#pragma unroll
        for (int p = 0; p < NSPLIT; p++) {
            float4 a = ((const float4*)g_s1p[p])[i];
            sx += a.x; sy += a.y; sz += a.z; sw += a.w;
        }
        ((float4*)g_s1)[i] = make_float4(sx*r, sy*r, sz*r, sw*r);
    }
}

// ============================ Kernel 4: GEMM2 (single-pass fp16, fused q-norm + mask, occ 2) ============================
__global__ void __launch_bounds__(256, 2)
k_g2(const float* __restrict__ Q, const void* __restrict__ mask,
     float* __restrict__ Out) {
    extern __shared__ __align__(16) char sm[];
    const uint32_t sb = smem_u32(sm);
    const int tid = threadIdx.x, lane = tid & 31, wid = tid >> 5;
    const int b = blockIdx.z, m0 = blockIdx.y * 128, n0 = blockIdx.x * 128;
    const float* Qb  = Q + (size_t)b * SS * DD;
    const float* s1b = g_s1 + (size_t)b * DD * DD;
    float* smul = (float*)(sm + 2 * BUF2);

    const int ar = tid >> 1, aq0 = tid & 1;
    const int blr = tid >> 3, bq0 = tid & 7;
    const int wm = (wid >> 2) * 64, wn = (wid & 3) * 32;
    const int rowA = lane & 15, colA = (lane >> 4) << 3;
    const int rowB = lane & 15, colB = (lane >> 4) << 3;

    float acc[4][4][4];
#pragma unroll
    for (int i = 0; i < 4; i++)
#pragma unroll
        for (int j = 0; j < 4; j++)
#pragma unroll
            for (int t = 0; t < 4; t++) acc[i][j][t] = 0.f;

    const bool msk = is_masked(mask, b * SS + m0 + ar);
    float qss = 0.f;
    float4 ra[4], rb[4];
    {
        const float* qr = Qb + (size_t)(m0 + ar) * DD;
#pragma unroll
        for (int j = 0; j < 4; j++) {
            ra[j] = *(const float4*)(qr + 4 * (aq0 + 2 * j));
            qss += ra[j].x*ra[j].x + ra[j].y*ra[j].y + ra[j].z*ra[j].z + ra[j].w*ra[j].w;
            if (msk) ra[j] = make_float4(1.f, 1.f, 1.f, 1.f);
            rb[j] = *(const float4*)(s1b + (size_t)blr * DD + n0 + 4 * (bq0 + 8 * j));
        }
    }
    {
        char* Ah = sm; char* Bh = sm + A2SZ;
#pragma unroll
        for (int j = 0; j < 4; j++) {
            int off = ar * P2 + 8 * (aq0 + 2 * j);
            *(uint2*)(Ah + off) = make_uint2(pack_h(ra[j].x, ra[j].y),
                                             pack_h(ra[j].z, ra[j].w));
            int offb = blr * P1 + 8 * (bq0 + 8 * j);
            *(uint2*)(Bh + offb) = make_uint2(pack_h(rb[j].x, rb[j].y),
                                              pack_h(rb[j].z, rb[j].w));
        }
    }
    __syncthreads();

    for (int c = 0; c < NCH2; c++) {
        if (c + 1 < NCH2) {
            int k0 = (c + 1) * 32;
            const float* qr = Qb + (size_t)(m0 + ar) * DD + k0;
#pragma unroll
            for (int j = 0; j < 4; j++) {
                ra[j] = *(const float4*)(qr + 4 * (aq0 + 2 * j));
                qss += ra[j].x*ra[j].x + ra[j].y*ra[j].y + ra[j].z*ra[j].z + ra[j].w*ra[j].w;
                if (msk) ra[j] = make_float4(1.f, 1.f, 1.f, 1.f);
                rb[j] = *(const float4*)(s1b + (size_t)(k0 + blr) * DD + n0 + 4 * (bq0 + 8 * j));
            }
        }
        const uint32_t ub = sb + (uint32_t)(c & 1) * BUF2;
        const uint32_t uAh = ub, uBh = ub + A2SZ;
#pragma unroll
        for (int ks = 0; ks < 32; ks += 16) {
            uint32_t ah[4][4], bh[4][2];
#pragma unroll
            for (int mf = 0; mf < 4; mf++) {
                uint32_t a = (uint32_t)((wm + mf * 16 + rowA) * P2 + 2 * (ks + colA));
                ldsm_x4(ah[mf], uAh + a);
            }
#pragma unroll
            for (int nb = 0; nb < 2; nb++) {
                uint32_t a = (uint32_t)((ks + rowB) * P1 + 2 * (wn + nb * 16 + colB));
                ldsm_x4t(&bh[nb * 2][0], uBh + a);
            }
#pragma unroll
            for (int mi = 0; mi < 4; mi++)
#pragma unroll
                for (int ni = 0; ni < 4; ni++)
                    mma_f16(acc[mi][ni], ah[mi], bh[ni]);
        }
        if (c + 1 < NCH2) {
            char* bp = sm + ((c + 1) & 1) * BUF2;
            char* Ah = bp; char* Bh = bp + A2SZ;
#pragma unroll
            for (int j = 0; j < 4; j++) {
                int off = ar * P2 + 8 * (aq0 + 2 * j);
                *(uint2*)(Ah + off) = make_uint2(pack_h(ra[j].x, ra[j].y),
                                                 pack_h(ra[j].z, ra[j].w));
                int offb = blr * P1 + 8 * (bq0 + 8 * j);
                *(uint2*)(Bh + offb) = make_uint2(pack_h(rb[j].x, rb[j].y),
                                                  pack_h(rb[j].z, rb[j].w));
            }
        }
        __syncthreads();
    }

    qss += __shfl_xor_sync(0xFFFFFFFFu, qss, 1);
    if (aq0 == 0) smul[ar] = msk ? 0.0f : 1.0f / qss;
    __syncthreads();

    const float sc = 1.0f / 256.0f;
    const int r0 = lane >> 2, cp = (lane & 3) * 2;
#pragma unroll
    for (int mi = 0; mi < 4; mi++) {
        int m1 = m0 + wm + mi * 16 + r0;
        int m2 = m1 + 8;
        float mu1 = smul[m1 - m0], mu2 = smul[m2 - m0];
        float s1f = (mu1 == 0.0f) ? (NEGV * sc) : mu1 * sc;
        float s2f = (mu2 == 0.0f) ? (NEGV * sc) : mu2 * sc;
        float* o1 = Out + ((size_t)b * SS + m1) * DD;
        float* o2 = Out + ((size_t)b * SS + m2) * DD;
#pragma unroll
        for (int ni = 0; ni < 4; ni++) {
            int n = n0 + wn + ni * 8 + cp;
            *(float2*)(o1 + n) = make_float2(acc[mi][ni][0] * s1f, acc[mi][ni][1] * s1f);
            *(float2*)(o2 + n) = make_float2(acc[mi][ni][2] * s2f, acc[mi][ni][3] * s2f);
        }
    }
}

// ===========================================================================
extern "C" void kernel_launch(void* const* d_in, const int* in_sizes, int n_in,
                              void* d_out, int out_size) {
    const float* q    = (const float*)d_in[0];
    const float* k    = (const float*)d_in[1];
    const float* v    = (const float*)d_in[2];
    const void*  mask = d_in[3];
    float* out = (float*)d_out;

    const int SMEM_G1 = 2 * BUF1;         // 34816
    const int SMEM_G2 = 2 * BUF2 + 512;   // 38400
    cudaFuncSetAttribute(k_g1, cudaFuncAttributeMaxDynamicSharedMemorySize, SMEM_G1);
    cudaFuncSetAttribute(k_g2, cudaFuncAttributeMaxDynamicSharedMemorySize, SMEM_G2);

    k_knorm<<<NROWS / 8, 256>>>(k, (const unsigned int*)mask);
    k_g1<<<dim3(4, NSPLIT, BB), 256, SMEM_G1>>>(k, v);
    k_reduce<<<(BB * DD * DD / 8) / 256, 256>>>();
    k_g2<<<dim3(2, SS / 128, BB), 256, SMEM_G2>>>(q, mask, out);
}